// round 9
// baseline (speedup 1.0000x reference)
#include <cuda_runtime.h>
#include <cuda_fp16.h>
#include <cstdint>

#define T_DIM 2048
#define F_DIM 256
#define B_DIM 64
#define BM 128
#define BN 128
#define NSEG 4

// ---------------- device scratch (no runtime allocs) ----------------
__device__ float g_part[B_DIM * NSEG * F_DIM];          // EMA segment partials
__device__ __align__(16) __half g_Wh[F_DIM * F_DIM];    // Wt[n][k] fp16

__device__ __forceinline__ uint32_t smem_u32(const void* p) {
    uint32_t a;
    asm("{ .reg .u64 t; cvta.to.shared.u64 t, %1; cvt.u32.u64 %0, t; }" : "=r"(a) : "l"(p));
    return a;
}

#define LDSM4(r, addr)                                                              \
    asm volatile("ldmatrix.sync.aligned.m8n8.x4.shared.b16 {%0,%1,%2,%3}, [%4];"    \
                 : "=r"((r)[0]), "=r"((r)[1]), "=r"((r)[2]), "=r"((r)[3])           \
                 : "r"(addr))

#define MMA_F16(d, a, b0, b1)                                                       \
    asm volatile("mma.sync.aligned.m16n8k16.row.col.f32.f16.f16.f32 "               \
                 "{%0,%1,%2,%3}, {%4,%5,%6,%7}, {%8,%9}, {%0,%1,%2,%3};"            \
                 : "+f"((d)[0]), "+f"((d)[1]), "+f"((d)[2]), "+f"((d)[3])           \
                 : "r"((a)[0]), "r"((a)[1]), "r"((a)[2]), "r"((a)[3]),              \
                   "r"(b0), "r"(b1))

#define CPA16(sdst, gsrc)                                                           \
    asm volatile("cp.async.cg.shared.global [%0], [%1], 16;"                        \
                 :: "r"((uint32_t)(sdst)), "l"(gsrc) : "memory")
#define CPA_COMMIT()  asm volatile("cp.async.commit_group;" ::: "memory")
#define CPA_WAIT(n)   asm volatile("cp.async.wait_group %0;" :: "n"(n) : "memory")

// smem: A fp16 stages x2 (8KB) | B fp16 stages x3 (8KB) | lastpb 1KB
#define OFF_A0   0
#define OFF_B0   16384
#define OFF_LAST 40960
#define SMEM_BYTES (40960 + 1024 + 256)

// tile swizzle: row r (64B = 4x16B chunks): chunk slot = chunk ^ ((r>>1)&3)
__device__ __forceinline__ uint32_t tile_off(int r, int chunk) {
    return (uint32_t)(r * 64 + ((chunk ^ ((r >> 1) & 3)) << 4));
}

// ---------------------------------------------------------------------------
// Prep: blocks 0..255 -> W transpose+fp16; blocks 256..511 -> EMA partials.
// ---------------------------------------------------------------------------
__global__ void __launch_bounds__(256) prep_kernel(const float* __restrict__ W,
                                                   const float* __restrict__ x) {
    if (blockIdx.x < 256) {
        int idx = blockIdx.x * 256 + threadIdx.x;   // 65536
        int k = idx >> 8, n = idx & 255;
        g_Wh[n * 256 + k] = __float2half_rn(W[k * 256 + n]);
    } else {
        const int blk = blockIdx.x - 256;           // 0..255
        const int b = blk >> 2, s = blk & 3, f = threadIdx.x;
        float c128 = 0.8f;
        #pragma unroll
        for (int i = 0; i < 7; i++) c128 *= c128;   // 0.8^128
        float w = 0.2f;
        for (int i = 0; i < s; i++) w *= c128;
        const float* p = x + ((long)b * T_DIM + (T_DIM - 1 - s * 128)) * F_DIM + f;
        float acc = 0.0f;
        #pragma unroll 8
        for (int i = 0; i < 128; i++) {
            acc = fmaf(w, *p, acc);
            w *= 0.8f;
            p -= F_DIM;
        }
        g_part[(b * NSEG + s) * F_DIM + f] = acc;
    }
}

// ---------------------------------------------------------------------------
// GEMM via fp16 mma.sync, distance-2 prefetch both operands, full unroll.
// ---------------------------------------------------------------------------
__global__ void __launch_bounds__(256, 1) gemm_mma_kernel(const float* __restrict__ x,
                                                          const float* __restrict__ bias,
                                                          float* __restrict__ out) {
    extern __shared__ char smraw[];
    char* sb = (char*)(((uintptr_t)smraw + 127) & ~(uintptr_t)127);
    const uint32_t sbase = smem_u32(sb);
    const int tid = threadIdx.x;
    const int lane = tid & 31, wid = tid >> 5;
    const int wm = wid & 1, wn = wid >> 1;          // warp grid 2(m) x 4(n)
    const long rowBase = (long)blockIdx.y * BM;
    const int nBase = blockIdx.x * BN;

    // lastpb[f] = bias[f] + sum_s g_part[b][s][f]
    {
        const int bidx = (int)(rowBase >> 11);
        float v = bias[tid];
        #pragma unroll
        for (int s = 0; s < NSEG; s++) v += g_part[(bidx * NSEG + s) * F_DIM + tid];
        *(float*)(sb + OFF_LAST + tid * 4) = v;
    }

    // ---- A mapping: thread -> (row, 16-float k slice) ----
    const int arow = tid & 127;
    const int akc  = tid >> 7;                       // 0..1
    const float* aptr = x + (rowBase + arow) * 256 + akc * 16;
    const uint32_t a_sts0 = tile_off(arow, akc * 2);
    const uint32_t a_sts1 = tile_off(arow, akc * 2 + 1);

    // ---- B mapping: thread -> (n-row, 2 chunks) ----
    const int bn  = tid >> 1;
    const int bc0 = (tid & 1) * 2;
    const __half* bsrc = g_Wh + (nBase + bn) * 256 + bc0 * 8;
    const uint32_t b_dst0 = tile_off(bn, bc0);
    const uint32_t b_dst1 = tile_off(bn, bc0 + 1);

    const int ar = lane & 15;
    const int ac = lane >> 4;

    float acc[4][4][4];
    #pragma unroll
    for (int i = 0; i < 4; i++)
        #pragma unroll
        for (int j = 0; j < 4; j++)
            #pragma unroll
            for (int q = 0; q < 4; q++) acc[i][j][q] = 0.0f;

    float4 xv[2][4];   // xv[(c)&1] holds A[c] floats for this thread

    // ---- prologue ----
    #pragma unroll
    for (int i = 0; i < 4; i++) xv[0][i] = *(const float4*)(aptr + i * 4);
    CPA16(sbase + OFF_B0 + b_dst0, (const char*)bsrc);
    CPA16(sbase + OFF_B0 + b_dst1, (const char*)bsrc + 16);
    CPA_COMMIT();                                    // G0
    CPA16(sbase + OFF_B0 + 8192 + b_dst0, (const char*)(bsrc + 32));
    CPA16(sbase + OFF_B0 + 8192 + b_dst1, (const char*)(bsrc + 32) + 16);
    CPA_COMMIT();                                    // G1
    #pragma unroll
    for (int i = 0; i < 4; i++) xv[1][i] = *(const float4*)(aptr + 32 + i * 4);
    {   // convert + store A[0] into A-stage 0
        uint32_t h[8];
        const float* fv = (const float*)xv[0];
        #pragma unroll
        for (int j = 0; j < 8; j++) {
            __half2 hh = __floats2half2_rn(fv[2 * j], fv[2 * j + 1]);
            h[j] = *(uint32_t*)&hh;
        }
        *(uint4*)(sb + OFF_A0 + a_sts0) = make_uint4(h[0], h[1], h[2], h[3]);
        *(uint4*)(sb + OFF_A0 + a_sts1) = make_uint4(h[4], h[5], h[6], h[7]);
    }
    CPA_WAIT(1);                                     // G0 done
    __syncthreads();

    // ---- mainloop: fully unrolled, distance-2 prefetch ----
    #pragma unroll
    for (int c = 0; c < 8; c++) {
        const uint32_t curA = sbase + (uint32_t)(c & 1) * 8192;
        const uint32_t curB = sbase + OFF_B0 + (uint32_t)(c % 3) * 8192;

        if (c + 2 < 8) {
            #pragma unroll
            for (int i = 0; i < 4; i++)
                xv[c & 1][i] = *(const float4*)(aptr + (c + 2) * 32 + i * 4);
            const uint32_t nb = sbase + OFF_B0 + (uint32_t)((c + 2) % 3) * 8192;
            CPA16(nb + b_dst0, (const char*)(bsrc + (c + 2) * 32));
            CPA16(nb + b_dst1, (const char*)(bsrc + (c + 2) * 32) + 16);
            CPA_COMMIT();
        }

        // compute current stage
        #pragma unroll
        for (int ks = 0; ks < 2; ks++) {
            uint32_t ah[4][4], bh[2][4];
            const int chunk = ks * 2 + ac;
            #pragma unroll
            for (int mf = 0; mf < 4; mf++) {
                const int r = wm * 64 + mf * 16 + ar;
                LDSM4(ah[mf], curA + tile_off(r, chunk));
            }
            #pragma unroll
            for (int nb2 = 0; nb2 < 2; nb2++) {
                const int r = wn * 32 + nb2 * 16 + ar;
                LDSM4(bh[nb2], curB + tile_off(r, chunk));
            }
            #pragma unroll
            for (int mf = 0; mf < 4; mf++)
                #pragma unroll
                for (int nf = 0; nf < 4; nf++) {
                    const int nb2 = nf >> 1, p = nf & 1;
                    MMA_F16(acc[mf][nf], ah[mf], bh[nb2][p], bh[nb2][2 + p]);
                }
        }

        if (c + 1 < 8) {   // convert + store A[c+1]
            uint32_t h[8];
            const float* fv = (const float*)xv[(c + 1) & 1];
            #pragma unroll
            for (int j = 0; j < 8; j++) {
                __half2 hh = __floats2half2_rn(fv[2 * j], fv[2 * j + 1]);
                h[j] = *(uint32_t*)&hh;
            }
            char* dst = sb + ((c + 1) & 1) * 8192;
            *(uint4*)(dst + a_sts0) = make_uint4(h[0], h[1], h[2], h[3]);
            *(uint4*)(dst + a_sts1) = make_uint4(h[4], h[5], h[6], h[7]);
        }

        if (c < 6) CPA_WAIT(1);      // B[c+1] done, B[c+2] may stay in flight
        else if (c == 6) CPA_WAIT(0);
        __syncthreads();
    }

    // ---- epilogue: add lastpb, direct STG.64 ----
    const float* sl = (const float*)(sb + OFF_LAST);
    float lp[4][2];
    #pragma unroll
    for (int nf = 0; nf < 4; nf++) {
        const int cc = nBase + wn * 32 + nf * 8 + (lane & 3) * 2;
        lp[nf][0] = sl[cc];
        lp[nf][1] = sl[cc + 1];
    }
    #pragma unroll
    for (int mf = 0; mf < 4; mf++) {
        const long r0 = rowBase + wm * 64 + mf * 16 + (lane >> 2);
        #pragma unroll
        for (int nf = 0; nf < 4; nf++) {
            const int cc = nBase + wn * 32 + nf * 8 + (lane & 3) * 2;
            float2 v0 = make_float2(acc[mf][nf][0] + lp[nf][0], acc[mf][nf][1] + lp[nf][1]);
            float2 v1 = make_float2(acc[mf][nf][2] + lp[nf][0], acc[mf][nf][3] + lp[nf][1]);
            *(float2*)(out + r0 * 256 + cc)       = v0;
            *(float2*)(out + (r0 + 8) * 256 + cc) = v1;
        }
    }
}

extern "C" void kernel_launch(void* const* d_in, const int* in_sizes, int n_in,
                              void* d_out, int out_size) {
    const float* x    = (const float*)d_in[0];  // [64, 2048, 256]
    const float* W    = (const float*)d_in[1];  // [256, 256]
    const float* bias = (const float*)d_in[2];  // [256]
    float* out = (float*)d_out;                 // [64, 2048, 256]

    cudaFuncSetAttribute(gemm_mma_kernel, cudaFuncAttributeMaxDynamicSharedMemorySize, SMEM_BYTES);

    prep_kernel<<<512, 256>>>(W, x);
    gemm_mma_kernel<<<dim3(2, (B_DIM * T_DIM) / BM), 256, SMEM_BYTES>>>(x, bias, out);
}